// round 6
// baseline (speedup 1.0000x reference)
#include <cuda_runtime.h>
#include <cuda_fp16.h>
#include <math.h>

// ---------------- problem constants ----------------
#define NOPEN 64
#define NNIN  16
#define MAXN  65536
#define MAXE  4000000           // capacity for 2*nE incident entries
#define DTH   0.025f            // dt*H = (1/4)*0.1

// ---------------- device scratch ----------------
__device__ float   g_x[(size_t)MAXN * NOPEN];     // node features (f32)
__device__ __half2 g_p2[2][(size_t)MAXN * 32];    // ping-pong p = KN1 @ x (f16)
__device__ float   g_d2[MAXN];                    // 1/deg
__device__ int     g_deg[MAXN];
__device__ int     g_cnt[MAXN];                   // incident count (both endpoints)
__device__ int     g_off[MAXN];                   // CSR offsets
__device__ int     g_cur[MAXN];                   // fill cursors
__device__ int     g_adj[MAXE];                   // neighbor | (flag<<31)
__device__ float   g_wgt[MAXE];                   // sign-folded +-w^2

// ---------------- degree / norm / CSR build ----------------
__global__ void init_kernel(int nN) {
    int i = blockIdx.x * blockDim.x + threadIdx.x;
    if (i < nN) { g_deg[i] = 1; g_cnt[i] = 0; }
}
__global__ void deg_count_kernel(const int* __restrict__ jInd, int nE) {
    int i = blockIdx.x * blockDim.x + threadIdx.x;
    if (i < nE) atomicAdd(&g_deg[jInd[i]], 1);
}
__global__ void d2_kernel(int nN) {
    int i = blockIdx.x * blockDim.x + threadIdx.x;
    if (i < nN) g_d2[i] = 1.0f / (float)g_deg[i];
}
__global__ void hist_kernel(const int* __restrict__ iInd,
                            const int* __restrict__ jInd, int nE) {
    int i = blockIdx.x * blockDim.x + threadIdx.x;
    if (i < nE) {
        atomicAdd(&g_cnt[iInd[i]], 1);
        atomicAdd(&g_cnt[jInd[i]], 1);
    }
}
// single-block exclusive scan over g_cnt -> g_off, g_cur
__global__ void __launch_bounds__(1024)
scan_kernel(int nN) {
    __shared__ int sPart[1024];
    int tid = threadIdx.x;
    int chunk = (nN + 1023) >> 10;
    int beg = tid * chunk;
    int end = beg + chunk; if (end > nN) end = nN;
    int sum = 0;
    for (int i = beg; i < end; i++) sum += g_cnt[i];
    sPart[tid] = sum;
    __syncthreads();
    for (int d = 1; d < 1024; d <<= 1) {
        int v = (tid >= d) ? sPart[tid - d] : 0;
        __syncthreads();
        sPart[tid] += v;
        __syncthreads();
    }
    int off = sPart[tid] - sum;      // exclusive
    for (int i = beg; i < end; i++) {
        g_off[i] = off;
        g_cur[i] = off;
        off += g_cnt[i];
    }
}
__global__ void fill_kernel(const int* __restrict__ iInd,
                            const int* __restrict__ jInd, int nE) {
    int e = blockIdx.x * blockDim.x + threadIdx.x;
    if (e >= nE) return;
    int I = iInd[e], J = jInd[e];
    float w2 = g_d2[I] * g_d2[J];
    int pI = atomicAdd(&g_cur[I], 1);
    g_adj[pI] = J;                   // flag 0: s_I += w2*relu(p_I - p_J)
    g_wgt[pI] = w2;
    int pJ = atomicAdd(&g_cur[J], 1);
    g_adj[pJ] = I | 0x80000000;      // flag 1: s_J -= w2*relu(p_I - p_J)
    g_wgt[pJ] = -w2;
}

// ---------------- x0 = relu(K1Nopen @ xn), block-tiled ----------------
__global__ void __launch_bounds__(256)
x0_kernel(const float* __restrict__ xn, const float* __restrict__ K1, int nN) {
    __shared__ float sK[NNIN * NOPEN];       // sK[c*64+o] = K1[o][c]
    __shared__ float sX[NNIN][256];
    for (int idx = threadIdx.x; idx < NOPEN * NNIN; idx += blockDim.x) {
        int o = idx >> 4, c = idx & 15;
        sK[c * NOPEN + o] = K1[idx];
    }
    int n0 = blockIdx.x * 256;
    for (int idx = threadIdx.x; idx < NNIN * 256; idx += blockDim.x) {
        int c = idx >> 8, nn = idx & 255;
        int n = n0 + nn;
        sX[c][nn] = (n < nN) ? xn[(size_t)c * nN + n] : 0.f;
    }
    __syncthreads();

    int n = n0 + threadIdx.x;
    if (n >= nN) return;
    float* dst = &g_x[(size_t)n * NOPEN];
#pragma unroll
    for (int half = 0; half < 2; half++) {
        float acc[32];
#pragma unroll
        for (int o = 0; o < 32; o++) acc[o] = 0.f;
#pragma unroll
        for (int c = 0; c < NNIN; c++) {
            float xc = sX[c][threadIdx.x];
#pragma unroll
            for (int o = 0; o < 32; o++)
                acc[o] += sK[c * NOPEN + half * 32 + o] * xc;
        }
#pragma unroll
        for (int o4 = 0; o4 < 8; o4++) {
            float4 r;
            r.x = fmaxf(acc[4 * o4 + 0], 0.f);
            r.y = fmaxf(acc[4 * o4 + 1], 0.f);
            r.z = fmaxf(acc[4 * o4 + 2], 0.f);
            r.w = fmaxf(acc[4 * o4 + 3], 0.f);
            ((float4*)dst)[half * 8 + o4] = r;
        }
    }
}

// ---------------- pre: p0 = f16(KN1 @ x) (warp per node) ----------------
__global__ void __launch_bounds__(256)
pre_kernel(const float* __restrict__ KN1w, int nN) {
    __shared__ float sKp[64 * 66];           // sKp[k*66+o] = KN1[o][k]
    __shared__ float sRow[8][64];
    for (int idx = threadIdx.x; idx < 64 * 64; idx += blockDim.x) {
        int r = idx >> 6, c = idx & 63;
        sKp[c * 66 + r] = KN1w[idx];
    }
    __syncthreads();

    int lane = threadIdx.x & 31;
    int ws   = threadIdx.x >> 5;
    int n    = blockIdx.x * 8 + ws;
    if (n >= nN) return;
    int o0 = 2 * lane;

    float2 xv = *(const float2*)&g_x[(size_t)n * NOPEN + o0];
    sRow[ws][o0] = xv.x; sRow[ws][o0 + 1] = xv.y;
    __syncwarp();
    float p0 = 0.f, p1 = 0.f;
#pragma unroll 8
    for (int k = 0; k < 64; k++) {
        float xk = sRow[ws][k];
        float2 a = *(const float2*)&sKp[k * 66 + o0];
        p0 += a.x * xk;
        p1 += a.y * xk;
    }
    g_p2[0][(size_t)n * 32 + lane] = __floats2half2_rn(p0, p1);
}

// ---------------- fused layer: s (CSR gather), KN1^T, x update, new p ------
__global__ void __launch_bounds__(256)
layer_kernel(const float* __restrict__ KN1w, int nN, int inbuf, int last) {
    __shared__ float sKy[64 * 66];           // sKy[k*66+o] = KN1[k][o]
    __shared__ float sKp[64 * 66];           // sKp[k*66+o] = KN1[o][k]
    __shared__ float sRow[8][64];
    for (int idx = threadIdx.x; idx < 64 * 64; idx += blockDim.x) {
        int r = idx >> 6, c = idx & 63;
        float v = KN1w[idx];
        sKy[r * 66 + c] = v;
        sKp[c * 66 + r] = v;
    }
    __syncthreads();

    const __half2* pin  = g_p2[inbuf];
    __half2*       pout = g_p2[inbuf ^ 1];

    int lane = threadIdx.x & 31;
    int ws   = threadIdx.x >> 5;
    int n    = blockIdx.x * 8 + ws;
    if (n >= nN) return;

    int beg = g_off[n];
    int cnt = g_cnt[n];
    float2 ps = __half22float2(pin[(size_t)n * 32 + lane]);
    float accx = 0.f, accy = 0.f;

    for (int t0 = 0; t0 < cnt; t0 += 32) {
        int idx = t0 + lane;
        int a = 0; float wv = 0.f;
        if (idx < cnt) { a = g_adj[beg + idx]; wv = g_wgt[beg + idx]; }
#pragma unroll 8
        for (int c = 0; c < 32; c++) {
            int   av = __shfl_sync(0xffffffffu, a,  c);
            float wc = __shfl_sync(0xffffffffu, wv, c);
            int nbr = av & 0x7fffffff;
            float2 pb = __half22float2(pin[(size_t)nbr * 32 + lane]);
            float d0, d1;
            if (av < 0) { d0 = pb.x - ps.x; d1 = pb.y - ps.y; }
            else        { d0 = ps.x - pb.x; d1 = ps.y - pb.y; }
            accx += wc * fmaxf(d0, 0.f);   // wc==0 for padding lanes
            accy += wc * fmaxf(d1, 0.f);
        }
    }

    // stage s, apply KN1^T
    int o0 = 2 * lane;
    sRow[ws][o0] = accx; sRow[ws][o0 + 1] = accy;
    __syncwarp();
    float y0 = 0.f, y1 = 0.f;
#pragma unroll 8
    for (int k = 0; k < 64; k++) {
        float sk = sRow[ws][k];
        float2 av = *(const float2*)&sKy[k * 66 + o0];
        y0 += av.x * sk;
        y1 += av.y * sk;
    }
    size_t off = (size_t)n * NOPEN + o0;
    float2 xv = *(const float2*)&g_x[off];
    xv.x -= DTH * y0;
    xv.y -= DTH * y1;
    *(float2*)&g_x[off] = xv;

    if (!last) {
        __syncwarp();
        sRow[ws][o0] = xv.x; sRow[ws][o0 + 1] = xv.y;
        __syncwarp();
        float p0 = 0.f, p1 = 0.f;
#pragma unroll 8
        for (int k = 0; k < 64; k++) {
            float xk = sRow[ws][k];
            float2 av = *(const float2*)&sKp[k * 66 + o0];
            p0 += av.x * xk;
            p1 += av.y * xk;
        }
        pout[(size_t)n * 32 + lane] = __floats2half2_rn(p0, p1);
    }
}

// ---------------- out = log_softmax(KNclose @ x) ----------------
__global__ void __launch_bounds__(256)
final_kernel(const float* __restrict__ KC, float* __restrict__ out, int nN) {
    __shared__ float sC[64 * 66];            // sC[i*66+o] = KC[o][i]
    __shared__ float sX[8][64];
    for (int idx = threadIdx.x; idx < 64 * 64; idx += blockDim.x) {
        int o = idx >> 6, i = idx & 63;
        sC[i * 66 + o] = KC[idx];
    }
    __syncthreads();

    int lane = threadIdx.x & 31;
    int ws   = threadIdx.x >> 5;
    int n    = blockIdx.x * 8 + ws;
    if (n >= nN) return;
    int o0 = 2 * lane;

    float2 xv = *(const float2*)&g_x[(size_t)n * NOPEN + o0];
    sX[ws][o0] = xv.x; sX[ws][o0 + 1] = xv.y;
    __syncwarp();
    float v0 = 0.f, v1 = 0.f;
#pragma unroll 8
    for (int i = 0; i < 64; i++) {
        float xi = sX[ws][i];
        float2 a = *(const float2*)&sC[i * 66 + o0];
        v0 += a.x * xi;
        v1 += a.y * xi;
    }
    float m = fmaxf(v0, v1);
#pragma unroll
    for (int off = 16; off; off >>= 1)
        m = fmaxf(m, __shfl_xor_sync(0xffffffffu, m, off));
    float s = expf(v0 - m) + expf(v1 - m);
#pragma unroll
    for (int off = 16; off; off >>= 1)
        s += __shfl_xor_sync(0xffffffffu, s, off);
    float lse = m + logf(s);
    float2 r;
    r.x = v0 - lse;
    r.y = v1 - lse;
    *(float2*)&out[(size_t)n * NOPEN + o0] = r;
}

// ---------------- launch ----------------
extern "C" void kernel_launch(void* const* d_in, const int* in_sizes, int n_in,
                              void* d_out, int out_size) {
    const float* xn   = (const float*)d_in[0];
    const int*   iInd = (const int*)d_in[1];
    const int*   jInd = (const int*)d_in[2];
    int base = 3;
    if (n_in >= 7 && in_sizes[3] == 1) base = 4;
    const float* K1  = (const float*)d_in[base];
    const float* KN1 = (const float*)d_in[base + 1];
    const float* KC  = (const float*)d_in[base + 2];

    int nN = in_sizes[0] / NNIN;
    int nE = in_sizes[1];

    int nodeBlocks = (nN + 7) / 8;
    int nb256 = (nN + 255) / 256;
    int eb256 = (nE + 255) / 256;

    // CSR build + norm
    init_kernel<<<nb256, 256>>>(nN);
    deg_count_kernel<<<eb256, 256>>>(jInd, nE);
    d2_kernel<<<nb256, 256>>>(nN);
    hist_kernel<<<eb256, 256>>>(iInd, jInd, nE);
    scan_kernel<<<1, 1024>>>(nN);
    fill_kernel<<<eb256, 256>>>(iInd, jInd, nE);

    // network
    x0_kernel<<<nb256, 256>>>(xn, K1, nN);
    pre_kernel<<<nodeBlocks, 256>>>(KN1, nN);
    for (int l = 0; l < 4; l++)
        layer_kernel<<<nodeBlocks, 256>>>(KN1, nN, l & 1, l == 3 ? 1 : 0);
    final_kernel<<<nodeBlocks, 256>>>(KC, (float*)d_out, nN);
}

// round 8
// speedup vs baseline: 1.2165x; 1.2165x over previous
#include <cuda_runtime.h>
#include <cuda_fp16.h>
#include <math.h>

// ---------------- problem constants ----------------
#define NOPEN 64
#define NNIN  16
#define MAXN  65536
#define MAXE  4000000           // capacity for 2*nE incident entries
#define DTH   0.025f            // dt*H = (1/4)*0.1

// ---------------- device scratch ----------------
__device__ float    g_x[(size_t)MAXN * NOPEN];     // node features (f32)
__device__ __half2  g_p2[2][(size_t)MAXN * 32];    // ping-pong p = KN1 @ x (f16)
__device__ float    g_d2[MAXN];                    // 1/deg
__device__ int      g_deg[MAXN];
__device__ int      g_cnt[MAXN];                   // incident count
__device__ int      g_off[MAXN];                   // CSR offsets
__device__ int      g_cur[MAXN];                   // fill cursors
__device__ unsigned g_adj[MAXE];                   // (nbr<<16) | f16bits(+-w2)

// ---------------- init / fused count ----------------
__global__ void init_kernel(int nN) {
    int i = blockIdx.x * blockDim.x + threadIdx.x;
    if (i < nN) { g_deg[i] = 1; g_cnt[i] = 0; }
}
__global__ void count_kernel(const int* __restrict__ iInd,
                             const int* __restrict__ jInd, int nE) {
    int e = blockIdx.x * blockDim.x + threadIdx.x;
    if (e >= nE) return;
    int I = iInd[e], J = jInd[e];
    atomicAdd(&g_deg[J], 1);
    atomicAdd(&g_cnt[I], 1);
    atomicAdd(&g_cnt[J], 1);
}
__global__ void d2_kernel(int nN) {
    int i = blockIdx.x * blockDim.x + threadIdx.x;
    if (i < nN) g_d2[i] = 1.0f / (float)g_deg[i];
}
// single-block exclusive scan over g_cnt -> g_off, g_cur
__global__ void __launch_bounds__(1024)
scan_kernel(int nN) {
    __shared__ int sPart[1024];
    int tid = threadIdx.x;
    int chunk = (nN + 1023) >> 10;
    int beg = tid * chunk;
    int end = beg + chunk; if (end > nN) end = nN;
    int sum = 0;
    for (int i = beg; i < end; i++) sum += g_cnt[i];
    sPart[tid] = sum;
    __syncthreads();
    for (int d = 1; d < 1024; d <<= 1) {
        int v = (tid >= d) ? sPart[tid - d] : 0;
        __syncthreads();
        sPart[tid] += v;
        __syncthreads();
    }
    int off = sPart[tid] - sum;
    for (int i = beg; i < end; i++) {
        g_off[i] = off;
        g_cur[i] = off;
        off += g_cnt[i];
    }
}
__global__ void fill_kernel(const int* __restrict__ iInd,
                            const int* __restrict__ jInd, int nE) {
    int e = blockIdx.x * blockDim.x + threadIdx.x;
    if (e >= nE) return;
    int I = iInd[e], J = jInd[e];
    float w2 = g_d2[I] * g_d2[J];
    unsigned short hb = __half_as_ushort(__float2half(w2));
    int pI = atomicAdd(&g_cur[I], 1);
    g_adj[pI] = ((unsigned)J << 16) | hb;              // +w2: use fmax(t,0)
    int pJ = atomicAdd(&g_cur[J], 1);
    g_adj[pJ] = ((unsigned)I << 16) | hb | 0x8000u;    // -w2: use fmin(t,0)
}

// ---------------- x0 = relu(K1Nopen @ xn) ----------------
__global__ void __launch_bounds__(256)
x0_kernel(const float* __restrict__ xn, const float* __restrict__ K1, int nN) {
    __shared__ float sK[NNIN * NOPEN];       // sK[c*64+o] = K1[o][c]
    __shared__ float sX[NNIN][256];
    for (int idx = threadIdx.x; idx < NOPEN * NNIN; idx += blockDim.x) {
        int o = idx >> 4, c = idx & 15;
        sK[c * NOPEN + o] = K1[idx];
    }
    int n0 = blockIdx.x * 256;
    for (int idx = threadIdx.x; idx < NNIN * 256; idx += blockDim.x) {
        int c = idx >> 8, nn = idx & 255;
        int n = n0 + nn;
        sX[c][nn] = (n < nN) ? xn[(size_t)c * nN + n] : 0.f;
    }
    __syncthreads();

    int n = n0 + threadIdx.x;
    if (n >= nN) return;
    float* dst = &g_x[(size_t)n * NOPEN];
#pragma unroll
    for (int half = 0; half < 2; half++) {
        float acc[32];
#pragma unroll
        for (int o = 0; o < 32; o++) acc[o] = 0.f;
#pragma unroll
        for (int c = 0; c < NNIN; c++) {
            float xc = sX[c][threadIdx.x];
#pragma unroll
            for (int o = 0; o < 32; o++)
                acc[o] += sK[c * NOPEN + half * 32 + o] * xc;
        }
#pragma unroll
        for (int o4 = 0; o4 < 8; o4++) {
            float4 r;
            r.x = fmaxf(acc[4 * o4 + 0], 0.f);
            r.y = fmaxf(acc[4 * o4 + 1], 0.f);
            r.z = fmaxf(acc[4 * o4 + 2], 0.f);
            r.w = fmaxf(acc[4 * o4 + 3], 0.f);
            ((float4*)dst)[half * 8 + o4] = r;
        }
    }
}

// ---------------- pre: p0 = f16(KN1 @ x) (warp per node) ----------------
__global__ void __launch_bounds__(256)
pre_kernel(const float* __restrict__ KN1w, int nN) {
    __shared__ float sKp[64 * 66];           // sKp[k*66+o] = KN1[o][k]
    __shared__ float sRow[8][64];
    for (int idx = threadIdx.x; idx < 64 * 64; idx += blockDim.x) {
        int r = idx >> 6, c = idx & 63;
        sKp[c * 66 + r] = KN1w[idx];
    }
    __syncthreads();

    int lane = threadIdx.x & 31;
    int ws   = threadIdx.x >> 5;
    int n    = blockIdx.x * 8 + ws;
    if (n >= nN) return;
    int o0 = 2 * lane;

    float2 xv = *(const float2*)&g_x[(size_t)n * NOPEN + o0];
    sRow[ws][o0] = xv.x; sRow[ws][o0 + 1] = xv.y;
    __syncwarp();
    float p0 = 0.f, p1 = 0.f;
#pragma unroll 8
    for (int k = 0; k < 64; k++) {
        float xk = sRow[ws][k];
        float2 a = *(const float2*)&sKp[k * 66 + o0];
        p0 += a.x * xk;
        p1 += a.y * xk;
    }
    g_p2[0][(size_t)n * 32 + lane] = __floats2half2_rn(p0, p1);
}

// ---------------- fused layer ----------------
// gather s (CSR, f16 math, 16-deep load batches) -> KN1^T -> x update ->
// next p (mid layers) or KNclose+log_softmax (last layer).
__global__ void __launch_bounds__(256)
layer_kernel(const float* __restrict__ KN1w, const float* __restrict__ KC,
             float* __restrict__ out, int nN, int inbuf, int last) {
    __shared__ float sKy[64 * 66];           // sKy[k*66+o] = KN1[k][o]
    __shared__ float sKp[64 * 66];           // mid: KN1[o][k] ; last: KC[o][i]
    __shared__ float sRow[8][64];
    const float* P2 = last ? KC : KN1w;
    for (int idx = threadIdx.x; idx < 64 * 64; idx += blockDim.x) {
        int r = idx >> 6, c = idx & 63;
        sKy[r * 66 + c] = KN1w[idx];
        sKp[c * 66 + r] = P2[idx];
    }
    __syncthreads();

    const unsigned* pin  = (const unsigned*)g_p2[inbuf];
    __half2*        pout = g_p2[inbuf ^ 1];

    int lane = threadIdx.x & 31;
    int ws   = threadIdx.x >> 5;
    int n    = blockIdx.x * 8 + ws;
    if (n >= nN) return;

    int beg = g_off[n];
    int cnt = g_cnt[n];
    unsigned psu = pin[(size_t)n * 32 + lane];
    __half2 psh = *(__half2*)&psu;
    const __half2 zero2 = __float2half2_rn(0.f);
    __half2 accA = zero2, accB = zero2;

    for (int t0 = 0; t0 < cnt; t0 += 32) {
        int idx = t0 + lane;
        unsigned v = (idx < cnt) ? __ldg(&g_adj[beg + idx]) : 0u;  // w=+0 -> 0 contrib
#pragma unroll
        for (int h = 0; h < 2; h++) {
            unsigned vv[16], pbv[16];
#pragma unroll
            for (int c = 0; c < 16; c++)
                vv[c] = __shfl_sync(0xffffffffu, v, h * 16 + c);
#pragma unroll
            for (int c = 0; c < 16; c++)
                pbv[c] = __ldg(&pin[(size_t)(vv[c] >> 16) * 32 + lane]);
#pragma unroll
            for (int c = 0; c < 16; c++) {
                __half2 pb = *(__half2*)&pbv[c];
                __half2 t = __hsub2(psh, pb);
                unsigned short wb = (unsigned short)(vv[c] & 0x7fffu);
                __half wa = __ushort_as_half(wb);
                __half2 w2h = __half2half2(wa);
                __half2 d = (vv[c] & 0x8000u) ? __hmin2(t, zero2)
                                              : __hmax2(t, zero2);
                if (c & 1) accB = __hfma2(d, w2h, accB);
                else       accA = __hfma2(d, w2h, accA);
            }
        }
    }
    float2 sa = __half22float2(accA);
    float2 sb = __half22float2(accB);
    float sx = sa.x + sb.x, sy = sa.y + sb.y;

    // stage s, apply KN1^T
    int o0 = 2 * lane;
    sRow[ws][o0] = sx; sRow[ws][o0 + 1] = sy;
    __syncwarp();
    float y0 = 0.f, y1 = 0.f;
#pragma unroll 8
    for (int k = 0; k < 64; k++) {
        float sk = sRow[ws][k];
        float2 av = *(const float2*)&sKy[k * 66 + o0];
        y0 += av.x * sk;
        y1 += av.y * sk;
    }
    size_t off = (size_t)n * NOPEN + o0;
    float2 xv = *(const float2*)&g_x[off];
    xv.x -= DTH * y0;
    xv.y -= DTH * y1;

    __syncwarp();
    sRow[ws][o0] = xv.x; sRow[ws][o0 + 1] = xv.y;
    __syncwarp();
    float v0 = 0.f, v1 = 0.f;
#pragma unroll 8
    for (int k = 0; k < 64; k++) {
        float xk = sRow[ws][k];
        float2 av = *(const float2*)&sKp[k * 66 + o0];
        v0 += av.x * xk;
        v1 += av.y * xk;
    }

    if (!last) {
        *(float2*)&g_x[off] = xv;
        pout[(size_t)n * 32 + lane] = __floats2half2_rn(v0, v1);
    } else {
        // v0,v1 = logits; warp log_softmax over 64 outputs
        float m = fmaxf(v0, v1);
#pragma unroll
        for (int o = 16; o; o >>= 1)
            m = fmaxf(m, __shfl_xor_sync(0xffffffffu, m, o));
        float s = expf(v0 - m) + expf(v1 - m);
#pragma unroll
        for (int o = 16; o; o >>= 1)
            s += __shfl_xor_sync(0xffffffffu, s, o);
        float lse = m + logf(s);
        float2 r;
        r.x = v0 - lse;
        r.y = v1 - lse;
        *(float2*)&out[(size_t)n * NOPEN + o0] = r;
    }
}

// ---------------- launch ----------------
extern "C" void kernel_launch(void* const* d_in, const int* in_sizes, int n_in,
                              void* d_out, int out_size) {
    const float* xn   = (const float*)d_in[0];
    const int*   iInd = (const int*)d_in[1];
    const int*   jInd = (const int*)d_in[2];
    int base = 3;
    if (n_in >= 7 && in_sizes[3] == 1) base = 4;
    const float* K1  = (const float*)d_in[base];
    const float* KN1 = (const float*)d_in[base + 1];
    const float* KC  = (const float*)d_in[base + 2];

    int nN = in_sizes[0] / NNIN;
    int nE = in_sizes[1];

    int nodeBlocks = (nN + 7) / 8;
    int nb256 = (nN + 255) / 256;
    int eb256 = (nE + 255) / 256;

    // CSR build + norm
    init_kernel<<<nb256, 256>>>(nN);
    count_kernel<<<eb256, 256>>>(iInd, jInd, nE);
    d2_kernel<<<nb256, 256>>>(nN);
    scan_kernel<<<1, 1024>>>(nN);
    fill_kernel<<<eb256, 256>>>(iInd, jInd, nE);

    // network
    x0_kernel<<<nb256, 256>>>(xn, K1, nN);
    pre_kernel<<<nodeBlocks, 256>>>(KN1, nN);
    for (int l = 0; l < 4; l++)
        layer_kernel<<<nodeBlocks, 256>>>(KN1, KC, (float*)d_out, nN, l & 1,
                                          l == 3 ? 1 : 0);
}

// round 9
// speedup vs baseline: 1.3648x; 1.1219x over previous
#include <cuda_runtime.h>
#include <cuda_fp16.h>
#include <math.h>

// ---------------- problem constants ----------------
#define NOPEN 64
#define NNIN  16
#define MAXN  65536
#define MAXE  4000000           // capacity for 2*nE incident entries
#define DTH   0.025f            // dt*H = (1/4)*0.1
#define SCAN_B 256              // block threads for scan
#define SCAN_E 1024             // elements per scan block

// ---------------- device scratch ----------------
__device__ float    g_x[(size_t)MAXN * NOPEN];     // node features (f32)
__device__ __half2  g_p2[2][(size_t)MAXN * 32];    // ping-pong p = KN1 @ x (f16)
__device__ float    g_d2[MAXN];                    // 1/deg
__device__ int      g_deg[MAXN];
__device__ int      g_cnt[MAXN];                   // incident count
__device__ int      g_off[MAXN];                   // CSR offsets
__device__ int      g_cur[MAXN];                   // fill cursors
__device__ unsigned g_adj[MAXE];                   // (nbr<<16) | f16bits(+-w2)
__device__ int      g_bsum[256];                   // scan block sums
__device__ int      g_bpre[256];                   // scanned block sums

// ---------------- init / fused count ----------------
__global__ void init_kernel(int nN) {
    int i = blockIdx.x * blockDim.x + threadIdx.x;
    if (i < nN) { g_deg[i] = 1; g_cnt[i] = 0; }
}
__global__ void count_kernel(const int* __restrict__ iInd,
                             const int* __restrict__ jInd, int nE) {
    int e = blockIdx.x * blockDim.x + threadIdx.x;
    if (e >= nE) return;
    int I = iInd[e], J = jInd[e];
    atomicAdd(&g_deg[J], 1);
    atomicAdd(&g_cnt[I], 1);
    atomicAdd(&g_cnt[J], 1);
}
__global__ void d2_kernel(int nN) {
    int i = blockIdx.x * blockDim.x + threadIdx.x;
    if (i < nN) g_d2[i] = 1.0f / (float)g_deg[i];
}

// ---------------- 3-phase scan (coalesced) ----------------
__global__ void __launch_bounds__(SCAN_B)
scanA_kernel(int nPad4) {
    __shared__ int sSum[SCAN_B];
    int idx4 = blockIdx.x * SCAN_B + threadIdx.x;     // int4 index
    int4 v = (idx4 < nPad4) ? ((const int4*)g_cnt)[idx4]
                            : make_int4(0, 0, 0, 0);
    sSum[threadIdx.x] = v.x + v.y + v.z + v.w;
    __syncthreads();
    for (int d = SCAN_B / 2; d; d >>= 1) {
        if (threadIdx.x < d) sSum[threadIdx.x] += sSum[threadIdx.x + d];
        __syncthreads();
    }
    if (threadIdx.x == 0) g_bsum[blockIdx.x] = sSum[0];
}
__global__ void __launch_bounds__(256)
scanB_kernel(int nBlocks) {
    __shared__ int sV[256];
    int t = threadIdx.x;
    sV[t] = (t < nBlocks) ? g_bsum[t] : 0;
    __syncthreads();
    for (int d = 1; d < 256; d <<= 1) {
        int v = (t >= d) ? sV[t - d] : 0;
        __syncthreads();
        sV[t] += v;
        __syncthreads();
    }
    if (t < nBlocks) g_bpre[t] = sV[t] - g_bsum[t];   // exclusive
}
__global__ void __launch_bounds__(SCAN_B)
scanC_kernel(int nPad4) {
    __shared__ int sV[SCAN_B];
    int idx4 = blockIdx.x * SCAN_B + threadIdx.x;
    int4 v = (idx4 < nPad4) ? ((const int4*)g_cnt)[idx4]
                            : make_int4(0, 0, 0, 0);
    int tsum = v.x + v.y + v.z + v.w;
    sV[threadIdx.x] = tsum;
    __syncthreads();
    for (int d = 1; d < SCAN_B; d <<= 1) {
        int u = (threadIdx.x >= d) ? sV[threadIdx.x - d] : 0;
        __syncthreads();
        sV[threadIdx.x] += u;
        __syncthreads();
    }
    int base = g_bpre[blockIdx.x] + sV[threadIdx.x] - tsum;  // exclusive
    if (idx4 < nPad4) {
        int4 o;
        o.x = base;
        o.y = base + v.x;
        o.z = base + v.x + v.y;
        o.w = base + v.x + v.y + v.z;
        ((int4*)g_off)[idx4] = o;
        ((int4*)g_cur)[idx4] = o;
    }
}

__global__ void fill_kernel(const int* __restrict__ iInd,
                            const int* __restrict__ jInd, int nE) {
    int e = blockIdx.x * blockDim.x + threadIdx.x;
    if (e >= nE) return;
    int I = iInd[e], J = jInd[e];
    float w2 = g_d2[I] * g_d2[J];
    unsigned short hb = __half_as_ushort(__float2half(w2));
    int pI = atomicAdd(&g_cur[I], 1);
    g_adj[pI] = ((unsigned)J << 16) | hb;              // +w2: use fmax(t,0)
    int pJ = atomicAdd(&g_cur[J], 1);
    g_adj[pJ] = ((unsigned)I << 16) | hb | 0x8000u;    // -w2: use fmin(t,0)
}

// ---------------- x0 = relu(K1Nopen @ xn) ----------------
__global__ void __launch_bounds__(256)
x0_kernel(const float* __restrict__ xn, const float* __restrict__ K1, int nN) {
    __shared__ float sK[NNIN * NOPEN];       // sK[c*64+o] = K1[o][c]
    __shared__ float sX[NNIN][256];
    for (int idx = threadIdx.x; idx < NOPEN * NNIN; idx += blockDim.x) {
        int o = idx >> 4, c = idx & 15;
        sK[c * NOPEN + o] = K1[idx];
    }
    int n0 = blockIdx.x * 256;
    for (int idx = threadIdx.x; idx < NNIN * 256; idx += blockDim.x) {
        int c = idx >> 8, nn = idx & 255;
        int n = n0 + nn;
        sX[c][nn] = (n < nN) ? xn[(size_t)c * nN + n] : 0.f;
    }
    __syncthreads();

    int n = n0 + threadIdx.x;
    if (n >= nN) return;
    float* dst = &g_x[(size_t)n * NOPEN];
#pragma unroll
    for (int half = 0; half < 2; half++) {
        float acc[32];
#pragma unroll
        for (int o = 0; o < 32; o++) acc[o] = 0.f;
#pragma unroll
        for (int c = 0; c < NNIN; c++) {
            float xc = sX[c][threadIdx.x];
#pragma unroll
            for (int o = 0; o < 32; o++)
                acc[o] += sK[c * NOPEN + half * 32 + o] * xc;
        }
#pragma unroll
        for (int o4 = 0; o4 < 8; o4++) {
            float4 r;
            r.x = fmaxf(acc[4 * o4 + 0], 0.f);
            r.y = fmaxf(acc[4 * o4 + 1], 0.f);
            r.z = fmaxf(acc[4 * o4 + 2], 0.f);
            r.w = fmaxf(acc[4 * o4 + 3], 0.f);
            ((float4*)dst)[half * 8 + o4] = r;
        }
    }
}

// ---------------- pre: p0 = f16(KN1 @ x) (warp per node) ----------------
__global__ void __launch_bounds__(256)
pre_kernel(const float* __restrict__ KN1w, int nN) {
    __shared__ float sKp[64 * 66];           // sKp[k*66+o] = KN1[o][k]
    __shared__ float sRow[8][64];
    for (int idx = threadIdx.x; idx < 64 * 64; idx += blockDim.x) {
        int r = idx >> 6, c = idx & 63;
        sKp[c * 66 + r] = KN1w[idx];
    }
    __syncthreads();

    int lane = threadIdx.x & 31;
    int ws   = threadIdx.x >> 5;
    int n    = blockIdx.x * 8 + ws;
    if (n >= nN) return;
    int o0 = 2 * lane;

    float2 xv = *(const float2*)&g_x[(size_t)n * NOPEN + o0];
    sRow[ws][o0] = xv.x; sRow[ws][o0 + 1] = xv.y;
    __syncwarp();
    float p0 = 0.f, p1 = 0.f;
#pragma unroll 8
    for (int k = 0; k < 64; k++) {
        float xk = sRow[ws][k];
        float2 a = *(const float2*)&sKp[k * 66 + o0];
        p0 += a.x * xk;
        p1 += a.y * xk;
    }
    g_p2[0][(size_t)n * 32 + lane] = __floats2half2_rn(p0, p1);
}

// ---------------- fused layer ----------------
__global__ void __launch_bounds__(256)
layer_kernel(const float* __restrict__ KN1w, const float* __restrict__ KC,
             float* __restrict__ out, int nN, int inbuf, int last) {
    __shared__ float sKy[64 * 66];           // sKy[k*66+o] = KN1[k][o]
    __shared__ float sKp[64 * 66];           // mid: KN1[o][k] ; last: KC[o][i]
    __shared__ float sRow[8][64];
    const float* P2 = last ? KC : KN1w;
    for (int idx = threadIdx.x; idx < 64 * 64; idx += blockDim.x) {
        int r = idx >> 6, c = idx & 63;
        sKy[r * 66 + c] = KN1w[idx];
        sKp[c * 66 + r] = P2[idx];
    }
    __syncthreads();

    const unsigned* pin  = (const unsigned*)g_p2[inbuf];
    __half2*        pout = g_p2[inbuf ^ 1];

    int lane = threadIdx.x & 31;
    int ws   = threadIdx.x >> 5;
    int n    = blockIdx.x * 8 + ws;
    if (n >= nN) return;

    int beg = g_off[n];
    int cnt = g_cnt[n];
    unsigned psu = pin[(size_t)n * 32 + lane];
    __half2 psh = *(__half2*)&psu;
    const __half2 zero2 = __float2half2_rn(0.f);
    __half2 accA = zero2, accB = zero2;

    for (int t0 = 0; t0 < cnt; t0 += 32) {
        int idx = t0 + lane;
        unsigned v = (idx < cnt) ? __ldg(&g_adj[beg + idx]) : 0u;  // w=+0 -> 0 contrib
#pragma unroll
        for (int h = 0; h < 2; h++) {
            unsigned vv[16], pbv[16];
#pragma unroll
            for (int c = 0; c < 16; c++)
                vv[c] = __shfl_sync(0xffffffffu, v, h * 16 + c);
#pragma unroll
            for (int c = 0; c < 16; c++)
                pbv[c] = __ldg(&pin[(size_t)(vv[c] >> 16) * 32 + lane]);
#pragma unroll
            for (int c = 0; c < 16; c++) {
                __half2 pb = *(__half2*)&pbv[c];
                __half2 t = __hsub2(psh, pb);
                unsigned short wb = (unsigned short)(vv[c] & 0x7fffu);
                __half wa = __ushort_as_half(wb);
                __half2 w2h = __half2half2(wa);
                __half2 d = (vv[c] & 0x8000u) ? __hmin2(t, zero2)
                                              : __hmax2(t, zero2);
                if (c & 1) accB = __hfma2(d, w2h, accB);
                else       accA = __hfma2(d, w2h, accA);
            }
        }
    }
    float2 sa = __half22float2(accA);
    float2 sb = __half22float2(accB);
    float sx = sa.x + sb.x, sy = sa.y + sb.y;

    // stage s, apply KN1^T
    int o0 = 2 * lane;
    sRow[ws][o0] = sx; sRow[ws][o0 + 1] = sy;
    __syncwarp();
    float y0 = 0.f, y1 = 0.f;
#pragma unroll 8
    for (int k = 0; k < 64; k++) {
        float sk = sRow[ws][k];
        float2 av = *(const float2*)&sKy[k * 66 + o0];
        y0 += av.x * sk;
        y1 += av.y * sk;
    }
    size_t off = (size_t)n * NOPEN + o0;
    float2 xv = *(const float2*)&g_x[off];
    xv.x -= DTH * y0;
    xv.y -= DTH * y1;

    __syncwarp();
    sRow[ws][o0] = xv.x; sRow[ws][o0 + 1] = xv.y;
    __syncwarp();
    float v0 = 0.f, v1 = 0.f;
#pragma unroll 8
    for (int k = 0; k < 64; k++) {
        float xk = sRow[ws][k];
        float2 av = *(const float2*)&sKp[k * 66 + o0];
        v0 += av.x * xk;
        v1 += av.y * xk;
    }

    if (!last) {
        *(float2*)&g_x[off] = xv;
        pout[(size_t)n * 32 + lane] = __floats2half2_rn(v0, v1);
    } else {
        float m = fmaxf(v0, v1);
#pragma unroll
        for (int o = 16; o; o >>= 1)
            m = fmaxf(m, __shfl_xor_sync(0xffffffffu, m, o));
        float s = expf(v0 - m) + expf(v1 - m);
#pragma unroll
        for (int o = 16; o; o >>= 1)
            s += __shfl_xor_sync(0xffffffffu, s, o);
        float lse = m + logf(s);
        float2 r;
        r.x = v0 - lse;
        r.y = v1 - lse;
        *(float2*)&out[(size_t)n * NOPEN + o0] = r;
    }
}

// ---------------- launch ----------------
extern "C" void kernel_launch(void* const* d_in, const int* in_sizes, int n_in,
                              void* d_out, int out_size) {
    const float* xn   = (const float*)d_in[0];
    const int*   iInd = (const int*)d_in[1];
    const int*   jInd = (const int*)d_in[2];
    int base = 3;
    if (n_in >= 7 && in_sizes[3] == 1) base = 4;
    const float* K1  = (const float*)d_in[base];
    const float* KN1 = (const float*)d_in[base + 1];
    const float* KC  = (const float*)d_in[base + 2];

    int nN = in_sizes[0] / NNIN;
    int nE = in_sizes[1];

    int nodeBlocks = (nN + 7) / 8;
    int nb256 = (nN + 255) / 256;
    int eb256 = (nE + 255) / 256;
    int nPad4 = (nN + 3) / 4;                       // int4 count
    int scanBlocks = (nPad4 + SCAN_B - 1) / SCAN_B; // 1024 elems per block

    // CSR build + norm
    init_kernel<<<nb256, 256>>>(nN);
    count_kernel<<<eb256, 256>>>(iInd, jInd, nE);
    d2_kernel<<<nb256, 256>>>(nN);
    scanA_kernel<<<scanBlocks, SCAN_B>>>(nPad4);
    scanB_kernel<<<1, 256>>>(scanBlocks);
    scanC_kernel<<<scanBlocks, SCAN_B>>>(nPad4);
    fill_kernel<<<eb256, 256>>>(iInd, jInd, nE);

    // network
    x0_kernel<<<nb256, 256>>>(xn, K1, nN);
    pre_kernel<<<nodeBlocks, 256>>>(KN1, nN);
    for (int l = 0; l < 4; l++)
        layer_kernel<<<nodeBlocks, 256>>>(KN1, KC, (float*)d_out, nN, l & 1,
                                          l == 3 ? 1 : 0);
}